// round 7
// baseline (speedup 1.0000x reference)
#include <cuda_runtime.h>
#include <cuda_bf16.h>
#include <math.h>
#include <stdint.h>

typedef unsigned long long ull;

namespace {
constexpr int kB = 2, kC = 20000, kH = 64, kM = 8, kE = 200000, kP = 3;
constexpr int kNR = kB * kE;  // 400000 rows = 3125 * 128
constexpr int kNC = kB * kC;  // 40000
constexpr int TILE = 128;
constexpr int TBM = 512;  // msg threads (16 warps)
constexpr int TB = 512;   // node threads

// A row stride in bytes (152 bf16): 304 mod 128 = 48 -> ldmatrix conflict-free
constexpr int ASTR = 304;

// msg smem byte offsets
constexpr int A_HI = 0;            // 128*304 = 38912
constexpr int A_LO = 38912;        // 38912
constexpr int W1FH = 77824;        // 18432
constexpr int W1FL = 96256;        // 18432
constexpr int W2FH = 114688;       // 8192
constexpr int W2FL = 122880;       // 8192
constexpr int P1FH = 131072;       // 8192
constexpr int P1FL = 139264;       // 8192
constexpr int S_INV = 147456;      // 128*16
constexpr int S_REL = 149504;      // 128*12 -> 1536
constexpr int S_GATE = 151040;     // 256*4
constexpr int S_DST = 152064;      // 512
constexpr int S_FS = 152576;       // 512
constexpr int S_FD = 153088;       // 512
constexpr int S_BIAS = 153600;     // 256 floats = 1024
constexpr int MSG_SMEM_BYTES = 154624;

// node_kernel shared layout (float offsets)
constexpr int NOFF_U1 = 0;
constexpr int NOFF_U2 = 8192;
constexpr int NOFF_UB1 = 12288;
constexpr int NOFF_UB2 = 12352;
constexpr int NOFF_HM = 12416;
constexpr int NOFF_IDG = 21120;
constexpr int NODE_SMEM_FLOATS = 21248;
}  // namespace

// Scratch (static device globals)
__device__ float g_agg[kNC * kH];
__device__ float g_posupd[kNC * kP];
__device__ float g_inv[kNR * 4];
__device__ float g_npos[kNC * kM * 3];
__device__ float g_np2[kNC * kM];
__device__ float g_cent[kNC * 3];
__device__ unsigned g_mbits[kC];
// mma B-fragment-ordered weight images (uint2 = 4 bf16 per lane per (kstep, ntile))
__device__ __align__(16) uint2 g_w1f_hi[9 * 8 * 32];
__device__ __align__(16) uint2 g_w1f_lo[9 * 8 * 32];
__device__ __align__(16) uint2 g_w2f_hi[4 * 8 * 32];
__device__ __align__(16) uint2 g_w2f_lo[4 * 8 * 32];
__device__ __align__(16) uint2 g_p1f_hi[4 * 8 * 32];
__device__ __align__(16) uint2 g_p1f_lo[4 * 8 * 32];

// ---------- helpers ----------
__device__ __forceinline__ uint32_t smem_u32(const void* p) {
  uint32_t a;
  asm("{ .reg .u64 t; cvta.to.shared.u64 t, %1; cvt.u32.u64 %0, t; }"
      : "=r"(a) : "l"(p));
  return a;
}
__device__ __forceinline__ void ldmx4(uint32_t* r, uint32_t addr) {
  asm volatile(
      "ldmatrix.sync.aligned.m8n8.x4.shared.b16 {%0,%1,%2,%3}, [%4];"
      : "=r"(r[0]), "=r"(r[1]), "=r"(r[2]), "=r"(r[3]) : "r"(addr));
}
__device__ __forceinline__ void mma_bf16(float* d, const uint32_t* a, uint2 b) {
  asm volatile(
      "mma.sync.aligned.m16n8k16.row.col.f32.bf16.bf16.f32 "
      "{%0,%1,%2,%3}, {%4,%5,%6,%7}, {%8,%9}, {%0,%1,%2,%3};"
      : "+f"(d[0]), "+f"(d[1]), "+f"(d[2]), "+f"(d[3])
      : "r"(a[0]), "r"(a[1]), "r"(a[2]), "r"(a[3]), "r"(b.x), "r"(b.y));
}
__device__ __forceinline__ void red_add_v2(float* p, float a, float b) {
  asm volatile("red.global.add.v2.f32 [%0], {%1, %2};" ::"l"(p), "f"(a), "f"(b)
               : "memory");
}
__device__ __forceinline__ void red_add_v4(float* p, float a, float b, float c,
                                           float d) {
  asm volatile("red.global.add.v4.f32 [%0], {%1, %2, %3, %4};" ::"l"(p), "f"(a),
               "f"(b), "f"(c), "f"(d)
               : "memory");
}
__device__ __forceinline__ float silu_f(float v) {
  return __fdividef(v, 1.f + __expf(-v));
}
__device__ __forceinline__ float bf16_resid(float x) {
  return x - __bfloat162float(__float2bfloat16(x));
}
__device__ __forceinline__ uint2 pack4(float a, float b, float c, float d) {
  __nv_bfloat162 p0 = __floats2bfloat162_rn(a, b);
  __nv_bfloat162 p1 = __floats2bfloat162_rn(c, d);
  uint2 r;
  r.x = *reinterpret_cast<uint32_t*>(&p0);
  r.y = *reinterpret_cast<uint32_t*>(&p1);
  return r;
}
// packed f32x2 (node kernel)
__device__ __forceinline__ ull dup2(float v) {
  ull r;
  asm("mov.b64 %0, {%1, %1};" : "=l"(r) : "f"(v));
  return r;
}
__device__ __forceinline__ void ffma2(ull& d, ull a, ull b) {
  asm("fma.rn.f32x2 %0, %1, %2, %0;" : "+l"(d) : "l"(a), "l"(b));
}
__device__ __forceinline__ void fma2_scale_bias(ull& d, ull a, ull b) {
  asm("fma.rn.f32x2 %0, %0, %1, %2;" : "+l"(d) : "l"(a), "l"(b));
}
__device__ __forceinline__ float2 unpack2(ull v) {
  float2 f;
  asm("mov.b64 {%0, %1}, %2;" : "=f"(f.x), "=f"(f.y) : "l"(v));
  return f;
}

// ---------- prep kernels ----------
__global__ void zero_kernel() {
  int i = blockIdx.x * blockDim.x + threadIdx.x;
  if (i < kNC * kH) g_agg[i] = 0.f;
  if (i < kNC * kP) g_posupd[i] = 0.f;
}

// build B-fragment-ordered bf16-split weight images
__global__ void wfrag_kernel(const float* __restrict__ W1,
                             const float* __restrict__ W2,
                             const float* __restrict__ P1) {
  int idx = blockIdx.x * blockDim.x + threadIdx.x;
  if (idx < 9 * 8 * 32) {
    int lane = idx & 31, nt = (idx >> 5) & 7, ks = idx >> 8;
    int n = nt * 8 + (lane >> 2);
    int k0 = ks * 16 + 2 * (lane & 3);
    float v0 = (k0 < 132) ? W1[k0 * 64 + n] : 0.f;
    float v1 = (k0 + 1 < 132) ? W1[(k0 + 1) * 64 + n] : 0.f;
    float v2 = (k0 + 8 < 132) ? W1[(k0 + 8) * 64 + n] : 0.f;
    float v3 = (k0 + 9 < 132) ? W1[(k0 + 9) * 64 + n] : 0.f;
    g_w1f_hi[idx] = pack4(v0, v1, v2, v3);
    g_w1f_lo[idx] =
        pack4(bf16_resid(v0), bf16_resid(v1), bf16_resid(v2), bf16_resid(v3));
  }
  if (idx < 4 * 8 * 32) {
    int lane = idx & 31, nt = (idx >> 5) & 7, ks = idx >> 8;
    int n = nt * 8 + (lane >> 2);
    int k0 = ks * 16 + 2 * (lane & 3);
    float v0 = W2[k0 * 64 + n], v1 = W2[(k0 + 1) * 64 + n];
    float v2 = W2[(k0 + 8) * 64 + n], v3 = W2[(k0 + 9) * 64 + n];
    g_w2f_hi[idx] = pack4(v0, v1, v2, v3);
    g_w2f_lo[idx] =
        pack4(bf16_resid(v0), bf16_resid(v1), bf16_resid(v2), bf16_resid(v3));
    float p0 = P1[k0 * 64 + n], p1 = P1[(k0 + 1) * 64 + n];
    float p2 = P1[(k0 + 8) * 64 + n], p3 = P1[(k0 + 9) * 64 + n];
    g_p1f_hi[idx] = pack4(p0, p1, p2, p3);
    g_p1f_lo[idx] =
        pack4(bf16_resid(p0), bf16_resid(p1), bf16_resid(p2), bf16_resid(p3));
  }
}

__global__ void prep_kernel(const float* __restrict__ positions,
                            const int* __restrict__ cni,
                            const float* __restrict__ mask) {
  int i = blockIdx.x * blockDim.x + threadIdx.x;
  if (i >= kNC) return;
  int b = i / kC, c = i - b * kC;
  float sx = 0.f, sy = 0.f, sz = 0.f, cnt = 0.f;
  unsigned bits = 0;
#pragma unroll
  for (int m = 0; m < kM; m++) {
    int idx = cni[c * kM + m];
    const float* p = positions + ((size_t)b * kC + idx) * kP;
    float x = p[0], y = p[1], z = p[2];
    g_npos[((size_t)i * kM + m) * 3 + 0] = x;
    g_npos[((size_t)i * kM + m) * 3 + 1] = y;
    g_npos[((size_t)i * kM + m) * 3 + 2] = z;
    g_np2[i * kM + m] = x * x + y * y + z * z;
    float mk = mask[c * kM + m];
    if (mk > 0.f) { bits |= (1u << m); sx += x; sy += y; sz += z; cnt += 1.f; }
  }
  float den = fmaxf(cnt, 1e-12f);
  g_cent[i * 3 + 0] = sx / den;
  g_cent[i * 3 + 1] = sy / den;
  g_cent[i * 3 + 2] = sz / den;
  if (b == 0) g_mbits[c] = bits;
}

__global__ void __launch_bounds__(256) inv_kernel(
    const float* __restrict__ positions, const int* __restrict__ ei) {
  int g = blockIdx.x * blockDim.x + threadIdx.x;
  if (g >= kNR) return;
  int b = g / kE, e = g - b * kE;
  int src = ei[e], dst = ei[kE + e];
  int is = b * kC + src, id = b * kC + dst;

  float sp[24], dp[24], sp2[8], dp2[8];
  {
    const float4* a = (const float4*)(g_npos + (size_t)is * 24);
    float4* o = (float4*)sp;
#pragma unroll
    for (int q = 0; q < 6; q++) o[q] = a[q];
    const float4* a2 = (const float4*)(g_npos + (size_t)id * 24);
    float4* o2 = (float4*)dp;
#pragma unroll
    for (int q = 0; q < 6; q++) o2[q] = a2[q];
    const float4* s2 = (const float4*)(g_np2 + (size_t)is * 8);
    ((float4*)sp2)[0] = s2[0]; ((float4*)sp2)[1] = s2[1];
    const float4* d2 = (const float4*)(g_np2 + (size_t)id * 8);
    ((float4*)dp2)[0] = d2[0]; ((float4*)dp2)[1] = d2[1];
  }
  unsigned mx = g_mbits[src], my = g_mbits[dst];
  float pairwise = 0.f, hxy = 0.f;
  float colmin[8];
#pragma unroll
  for (int n = 0; n < 8; n++) colmin[n] = 3.4e38f;
#pragma unroll
  for (int m = 0; m < 8; m++) {
    if ((mx >> m) & 1) {
      float rowmin = 3.4e38f;
      float ax = sp[m * 3], ay = sp[m * 3 + 1], az = sp[m * 3 + 2], a2 = sp2[m];
#pragma unroll
      for (int n = 0; n < 8; n++) {
        if ((my >> n) & 1) {
          float s = a2 + dp2[n] -
                    2.f * (ax * dp[n * 3] + ay * dp[n * 3 + 1] + az * dp[n * 3 + 2]);
          float d = sqrtf(fmaxf(s, 0.f) + 1e-12f);
          pairwise += d;
          rowmin = fminf(rowmin, d);
          colmin[n] = fminf(colmin[n], d);
        }
      }
      hxy = fmaxf(hxy, rowmin);
    }
  }
  float hyx = 0.f;
#pragma unroll
  for (int n = 0; n < 8; n++)
    if ((my >> n) & 1) hyx = fmaxf(hyx, colmin[n]);
  float haus = fmaxf(hxy, hyx);

  float c0 = g_cent[is * 3 + 0] - g_cent[id * 3 + 0];
  float c1 = g_cent[is * 3 + 1] - g_cent[id * 3 + 1];
  float c2 = g_cent[is * 3 + 2] - g_cent[id * 3 + 2];
  float centroid = sqrtf(c0 * c0 + c1 * c1 + c2 * c2);

  const float* ps = positions + (size_t)is * kP;
  const float* pd = positions + (size_t)id * kP;
  float r0 = ps[0] - pd[0], r1 = ps[1] - pd[1], r2 = ps[2] - pd[2];
  float dist = sqrtf(r0 * r0 + r1 * r1 + r2 * r2);

  ((float4*)g_inv)[g] = make_float4(dist, pairwise, centroid, haus);
}

// ---------- msg kernel: warp-level bf16 mma ----------
__global__ void __launch_bounds__(TBM) msg_mma(
    const float* __restrict__ features, const float* __restrict__ positions,
    const int* __restrict__ ei, const float* __restrict__ b1,
    const float* __restrict__ b2, const float* __restrict__ pb1,
    const float* __restrict__ P2, const float* __restrict__ pb2) {
  extern __shared__ char smc[];
  const uint32_t sbase = smem_u32(smc);
  int tid = threadIdx.x;
  int warp = tid >> 5, lane = tid & 31;

  // copy weight fragment images + biases
  {
    uint4* dst = (uint4*)(smc + W1FH);
    const uint4* s1 = (const uint4*)g_w1f_hi;
    for (int i = tid; i < 18432 / 16; i += TBM) dst[i] = s1[i];
    uint4* dst2 = (uint4*)(smc + W1FL);
    const uint4* s2 = (const uint4*)g_w1f_lo;
    for (int i = tid; i < 18432 / 16; i += TBM) dst2[i] = s2[i];
    uint4* dst3 = (uint4*)(smc + W2FH);  // W2 hi, W2 lo, P1 hi, P1 lo contiguous
    const uint4* s3 = (const uint4*)g_w2f_hi;
    for (int i = tid; i < 8192 / 16; i += TBM) dst3[i] = s3[i];
    uint4* dst4 = (uint4*)(smc + W2FL);
    const uint4* s4 = (const uint4*)g_w2f_lo;
    for (int i = tid; i < 8192 / 16; i += TBM) dst4[i] = s4[i];
    uint4* dst5 = (uint4*)(smc + P1FH);
    const uint4* s5 = (const uint4*)g_p1f_hi;
    for (int i = tid; i < 8192 / 16; i += TBM) dst5[i] = s5[i];
    uint4* dst6 = (uint4*)(smc + P1FL);
    const uint4* s6 = (const uint4*)g_p1f_lo;
    for (int i = tid; i < 8192 / 16; i += TBM) dst6[i] = s6[i];
  }
  float* sb1 = (float*)(smc + S_BIAS);
  float* sb2 = sb1 + 64;
  float* spb1 = sb1 + 128;
  float* sP2 = sb1 + 192;
  if (tid < 64) {
    sb1[tid] = b1[tid];
    sb2[tid] = b2[tid];
    spb1[tid] = pb1[tid];
    sP2[tid] = P2[tid];
  }
  float pb2v = pb2[0];

  float* sInv = (float*)(smc + S_INV);
  float* sRel = (float*)(smc + S_REL);
  float* sGate = (float*)(smc + S_GATE);
  int* sDst = (int*)(smc + S_DST);
  int* sFs = (int*)(smc + S_FS);
  int* sFd = (int*)(smc + S_FD);
  if (tid < TILE) {
    int gr = blockIdx.x * TILE + tid;
    int b = gr / kE, e = gr - b * kE;
    int src = ei[e], dst = ei[kE + e];
    int is = b * kC + src, id = b * kC + dst;
    sFs[tid] = is * kH;
    sFd[tid] = id * kH;
    sDst[tid] = id;
    ((float4*)sInv)[tid] = ((const float4*)g_inv)[gr];
    const float* ps = positions + (size_t)is * kP;
    const float* pd = positions + (size_t)id * kP;
    sRel[tid * 3 + 0] = ps[0] - pd[0];
    sRel[tid * 3 + 1] = ps[1] - pd[1];
    sRel[tid * 3 + 2] = ps[2] - pd[2];
  }
  __syncthreads();

  // ---- convert X to bf16 hi/lo in smem (4 threads/row) ----
  {
    int row = tid >> 2, p = tid & 3;
    const float* src = (p < 2) ? (features + sFs[row] + p * 32)
                               : (features + sFd[row] + (p - 2) * 32);
    uint32_t colbase = (p < 2) ? (uint32_t)(p * 32) : (uint32_t)(64 + (p - 2) * 32);
    char* ah = smc + A_HI + row * ASTR;
    char* al = smc + A_LO + row * ASTR;
#pragma unroll
    for (int q = 0; q < 8; q++) {
      float4 v = ((const float4*)src)[q];
      uint32_t off = (colbase + q * 4) * 2;
      *(uint2*)(ah + off) = pack4(v.x, v.y, v.z, v.w);
      *(uint2*)(al + off) = pack4(bf16_resid(v.x), bf16_resid(v.y),
                                  bf16_resid(v.z), bf16_resid(v.w));
    }
    if (p == 3) {
      float4 iv = ((const float4*)sInv)[row];
      *(uint2*)(ah + 256) = pack4(iv.x, iv.y, iv.z, iv.w);
      *(uint2*)(al + 256) = pack4(bf16_resid(iv.x), bf16_resid(iv.y),
                                  bf16_resid(iv.z), bf16_resid(iv.w));
      uint2 z = make_uint2(0, 0);
      *(uint2*)(ah + 264) = z; *(uint2*)(ah + 272) = z; *(uint2*)(ah + 280) = z;
      *(uint2*)(al + 264) = z; *(uint2*)(al + 272) = z; *(uint2*)(al + 280) = z;
    }
  }
  __syncthreads();

  // warp tile coords
  int mrow0 = (warp >> 1) * 16;
  int nhalf = warp & 1, nbase = nhalf * 32;
  uint32_t aRow =
      (uint32_t)((mrow0 + (lane & 7) + ((lane >> 3) & 1) * 8) * ASTR +
                 ((lane >> 4) * 8) * 2);
  const uint2* w1fh = (const uint2*)(smc + W1FH);
  const uint2* w1fl = (const uint2*)(smc + W1FL);
  const uint2* w2fh = (const uint2*)(smc + W2FH);
  const uint2* w2fl = (const uint2*)(smc + W2FL);
  const uint2* p1fh = (const uint2*)(smc + P1FH);
  const uint2* p1fl = (const uint2*)(smc + P1FL);

  int r0 = mrow0 + (lane >> 2);
  int cq = 2 * (lane & 3);

  float acc[4][4];
#pragma unroll
  for (int nt = 0; nt < 4; nt++)
#pragma unroll
    for (int j = 0; j < 4; j++) acc[nt][j] = 0.f;

  // ---- GEMM1: X @ W1 (3-term split) ----
#pragma unroll
  for (int ks = 0; ks < 9; ks++) {
    uint32_t ah[4], al[4];
    ldmx4(ah, sbase + A_HI + aRow + ks * 32);
    ldmx4(al, sbase + A_LO + aRow + ks * 32);
#pragma unroll
    for (int nt = 0; nt < 4; nt++) {
      int fi = (ks * 8 + nhalf * 4 + nt) * 32 + lane;
      uint2 wh = w1fh[fi], wl = w1fl[fi];
      mma_bf16(acc[nt], ah, wh);
      mma_bf16(acc[nt], al, wh);
      mma_bf16(acc[nt], ah, wl);
    }
  }
  __syncthreads();  // all X reads done
  // epilogue: H = silu(D + b1), write bf16 hi/lo into A
#pragma unroll
  for (int nt = 0; nt < 4; nt++) {
    int c = nbase + nt * 8 + cq;
    float h00 = silu_f(acc[nt][0] + sb1[c]);
    float h01 = silu_f(acc[nt][1] + sb1[c + 1]);
    float h10 = silu_f(acc[nt][2] + sb1[c]);
    float h11 = silu_f(acc[nt][3] + sb1[c + 1]);
    uint32_t o0 = r0 * ASTR + c * 2, o1 = (r0 + 8) * ASTR + c * 2;
    uint2 dummy;
    __nv_bfloat162 hp0 = __floats2bfloat162_rn(h00, h01);
    __nv_bfloat162 hp1 = __floats2bfloat162_rn(h10, h11);
    *(__nv_bfloat162*)(smc + A_HI + o0) = hp0;
    *(__nv_bfloat162*)(smc + A_HI + o1) = hp1;
    __nv_bfloat162 lp0 = __floats2bfloat162_rn(bf16_resid(h00), bf16_resid(h01));
    __nv_bfloat162 lp1 = __floats2bfloat162_rn(bf16_resid(h10), bf16_resid(h11));
    *(__nv_bfloat162*)(smc + A_LO + o0) = lp0;
    *(__nv_bfloat162*)(smc + A_LO + o1) = lp1;
    (void)dummy;
  }
  __syncthreads();

  // ---- GEMM2: Msg = H @ W2 ----
#pragma unroll
  for (int nt = 0; nt < 4; nt++)
#pragma unroll
    for (int j = 0; j < 4; j++) acc[nt][j] = 0.f;
#pragma unroll
  for (int ks = 0; ks < 4; ks++) {
    uint32_t ah[4], al[4];
    ldmx4(ah, sbase + A_HI + aRow + ks * 32);
    ldmx4(al, sbase + A_LO + aRow + ks * 32);
#pragma unroll
    for (int nt = 0; nt < 4; nt++) {
      int fi = (ks * 8 + nhalf * 4 + nt) * 32 + lane;
      uint2 wh = w2fh[fi], wl = w2fl[fi];
      mma_bf16(acc[nt], ah, wh);
      mma_bf16(acc[nt], al, wh);
      mma_bf16(acc[nt], ah, wl);
    }
  }
  // add bias, scatter from registers (no smem needed)
  {
    int ob0 = sDst[r0], ob1 = sDst[r0 + 8];
#pragma unroll
    for (int nt = 0; nt < 4; nt++) {
      int c = nbase + nt * 8 + cq;
      acc[nt][0] += sb2[c];
      acc[nt][1] += sb2[c + 1];
      acc[nt][2] += sb2[c];
      acc[nt][3] += sb2[c + 1];
      red_add_v2(g_agg + (size_t)ob0 * kH + c, acc[nt][0], acc[nt][1]);
      red_add_v2(g_agg + (size_t)ob1 * kH + c, acc[nt][2], acc[nt][3]);
    }
  }
  __syncthreads();  // all H reads done; safe to overwrite with Msg
#pragma unroll
  for (int nt = 0; nt < 4; nt++) {
    int c = nbase + nt * 8 + cq;
    uint32_t o0 = r0 * ASTR + c * 2, o1 = (r0 + 8) * ASTR + c * 2;
    *(__nv_bfloat162*)(smc + A_HI + o0) =
        __floats2bfloat162_rn(acc[nt][0], acc[nt][1]);
    *(__nv_bfloat162*)(smc + A_HI + o1) =
        __floats2bfloat162_rn(acc[nt][2], acc[nt][3]);
    *(__nv_bfloat162*)(smc + A_LO + o0) =
        __floats2bfloat162_rn(bf16_resid(acc[nt][0]), bf16_resid(acc[nt][1]));
    *(__nv_bfloat162*)(smc + A_LO + o1) =
        __floats2bfloat162_rn(bf16_resid(acc[nt][2]), bf16_resid(acc[nt][3]));
  }
  __syncthreads();

  // ---- GEMM3: G = Msg @ P1 ----
#pragma unroll
  for (int nt = 0; nt < 4; nt++)
#pragma unroll
    for (int j = 0; j < 4; j++) acc[nt][j] = 0.f;
#pragma unroll
  for (int ks = 0; ks < 4; ks++) {
    uint32_t ah[4], al[4];
    ldmx4(ah, sbase + A_HI + aRow + ks * 32);
    ldmx4(al, sbase + A_LO + aRow + ks * 32);
#pragma unroll
    for (int nt = 0; nt < 4; nt++) {
      int fi = (ks * 8 + nhalf * 4 + nt) * 32 + lane;
      uint2 wh = p1fh[fi], wl = p1fl[fi];
      mma_bf16(acc[nt], ah, wh);
      mma_bf16(acc[nt], al, wh);
      mma_bf16(acc[nt], ah, wl);
    }
  }
  // gate partials: silu(G + pb1) . P2 per row
  {
    float p0 = 0.f, p1 = 0.f;
#pragma unroll
    for (int nt = 0; nt < 4; nt++) {
      int c = nbase + nt * 8 + cq;
      p0 = fmaf(silu_f(acc[nt][0] + spb1[c]), sP2[c], p0);
      p0 = fmaf(silu_f(acc[nt][1] + spb1[c + 1]), sP2[c + 1], p0);
      p1 = fmaf(silu_f(acc[nt][2] + spb1[c]), sP2[c], p1);
      p1 = fmaf(silu_f(acc[nt][3] + spb1[c + 1]), sP2[c + 1], p1);
    }
    p0 += __shfl_xor_sync(0xffffffffu, p0, 1);
    p0 += __shfl_xor_sync(0xffffffffu, p0, 2);
    p1 += __shfl_xor_sync(0xffffffffu, p1, 1);
    p1 += __shfl_xor_sync(0xffffffffu, p1, 2);
    if ((lane & 3) == 0) {
      sGate[nhalf * 128 + r0] = p0;
      sGate[nhalf * 128 + r0 + 8] = p1;
    }
  }
  __syncthreads();
  if (tid < TILE) {
    float wt = tanhf(sGate[tid] + sGate[128 + tid] + pb2v);
    int ob = sDst[tid];
    float* pp = g_posupd + (size_t)ob * kP;
    atomicAdd(pp + 0, wt * sRel[tid * 3 + 0]);
    atomicAdd(pp + 1, wt * sRel[tid * 3 + 1]);
    atomicAdd(pp + 2, wt * sRel[tid * 3 + 2]);
  }
}

// ---------- node kernel (fp32 FFMA2 path, unchanged) ----------
__device__ __forceinline__ void gemm16(const float* __restrict__ x0,
                                       const float* __restrict__ x1,
                                       const float* __restrict__ x2,
                                       const float* __restrict__ x3,
                                       const float* __restrict__ W, int cg,
                                       ull acc[4][2]) {
#pragma unroll 2
  for (int g = 0; g < 16; g++) {
    float4 xv0 = *(const float4*)(x0 + 4 * g);
    float4 xv1 = *(const float4*)(x1 + 4 * g);
    float4 xv2 = *(const float4*)(x2 + 4 * g);
    float4 xv3 = *(const float4*)(x3 + 4 * g);
#pragma unroll
    for (int kk = 0; kk < 4; kk++) {
      ulonglong2 w = *(const ulonglong2*)(W + (4 * g + kk) * 64 + cg * 4);
      ull d0 = dup2(((const float*)&xv0)[kk]);
      ull d1 = dup2(((const float*)&xv1)[kk]);
      ull d2 = dup2(((const float*)&xv2)[kk]);
      ull d3 = dup2(((const float*)&xv3)[kk]);
      ffma2(acc[0][0], d0, w.x);
      ffma2(acc[0][1], d0, w.y);
      ffma2(acc[1][0], d1, w.x);
      ffma2(acc[1][1], d1, w.y);
      ffma2(acc[2][0], d2, w.x);
      ffma2(acc[2][1], d2, w.y);
      ffma2(acc[3][0], d3, w.x);
      ffma2(acc[3][1], d3, w.y);
    }
  }
}

__global__ void __launch_bounds__(TB, 2) node_kernel(
    const float* __restrict__ features, const float* __restrict__ degree,
    const float* __restrict__ U1, const float* __restrict__ ub1,
    const float* __restrict__ U2, const float* __restrict__ ub2,
    float* __restrict__ out_feat) {
  extern __shared__ float smf[];
  float* sU1 = smf + NOFF_U1;
  float* sU2 = smf + NOFF_U2;
  float* sub1 = smf + NOFF_UB1;
  float* sub2 = smf + NOFF_UB2;
  float* sHM = smf + NOFF_HM;
  float* sInvD = smf + NOFF_IDG;

  int tid = threadIdx.x;
  for (int i = tid; i < 128 * 64; i += TB) sU1[i] = U1[i];
  for (int i = tid; i < 64 * 64; i += TB) sU2[i] = U2[i];
  if (tid < 64) { sub1[tid] = ub1[tid]; sub2[tid] = ub2[tid]; }

  if (tid < TILE) {
    int gr = blockIdx.x * TILE + tid;
    int grc = gr < kNC ? gr : kNC - 1;
    int c = grc % kC;
    sInvD[tid] = 1.f / fmaxf(degree[c], 1.f);
  }
  __syncthreads();

  int rg = tid >> 4, cg = tid & 15;
  int row0 = rg * 4;
  int gr0 = blockIdx.x * TILE + row0;
  int r0c = min(gr0 + 0, kNC - 1);
  int r1c = min(gr0 + 1, kNC - 1);
  int r2c = min(gr0 + 2, kNC - 1);
  int r3c = min(gr0 + 3, kNC - 1);

  ull acc[4][2];
#pragma unroll
  for (int i = 0; i < 4; i++) { acc[i][0] = 0ull; acc[i][1] = 0ull; }

  gemm16(g_agg + (size_t)r0c * kH, g_agg + (size_t)r1c * kH,
         g_agg + (size_t)r2c * kH, g_agg + (size_t)r3c * kH, sU1 + 64 * 64, cg,
         acc);
  {
    ull bias0 = *(const ull*)(sub1 + cg * 4 + 0);
    ull bias1 = *(const ull*)(sub1 + cg * 4 + 2);
#pragma unroll
    for (int i = 0; i < 4; i++) {
      ull dv = dup2(sInvD[row0 + i]);
      fma2_scale_bias(acc[i][0], dv, bias0);
      fma2_scale_bias(acc[i][1], dv, bias1);
    }
  }
  gemm16(features + (size_t)r0c * kH, features + (size_t)r1c * kH,
         features + (size_t)r2c * kH, features + (size_t)r3c * kH, sU1, cg,
         acc);
#pragma unroll
  for (int i = 0; i < 4; i++)
#pragma unroll
    for (int p = 0; p < 2; p++) {
      float2 h = unpack2(acc[i][p]);
      h.x = silu_f(h.x);
      h.y = silu_f(h.y);
      *(float2*)(sHM + (row0 + i) * 68 + cg * 4 + 2 * p) = h;
    }
  __syncthreads();

#pragma unroll
  for (int i = 0; i < 4; i++) {
    acc[i][0] = *(const ull*)(sub2 + cg * 4 + 0);
    acc[i][1] = *(const ull*)(sub2 + cg * 4 + 2);
  }
  gemm16(sHM + (row0 + 0) * 68, sHM + (row0 + 1) * 68, sHM + (row0 + 2) * 68,
         sHM + (row0 + 3) * 68, sU2, cg, acc);
#pragma unroll
  for (int i = 0; i < 4; i++) {
    int g2 = gr0 + i;
    if (g2 < kNC) {
      const float4 f = ((const float4*)(features + (size_t)g2 * kH))[cg];
      float2 v0 = unpack2(acc[i][0]);
      float2 v1 = unpack2(acc[i][1]);
      float4 o;
      o.x = f.x + v0.x;
      o.y = f.y + v0.y;
      o.z = f.z + v1.x;
      o.w = f.w + v1.y;
      ((float4*)(out_feat + (size_t)g2 * kH))[cg] = o;
    }
  }
}

__global__ void pos_kernel(const float* __restrict__ positions,
                           float* __restrict__ out_pos) {
  int i = blockIdx.x * blockDim.x + threadIdx.x;
  if (i < kNC * kP) out_pos[i] = positions[i] + g_posupd[i];
}

extern "C" void kernel_launch(void* const* d_in, const int* in_sizes, int n_in,
                              void* d_out, int out_size) {
  const float* features = (const float*)d_in[0];
  const float* positions = (const float*)d_in[1];
  const int* edge_index = (const int*)d_in[2];
  const float* degree = (const float*)d_in[3];
  const int* cni = (const int*)d_in[4];
  const float* mask = (const float*)d_in[5];
  const float* W1 = (const float*)d_in[6];
  const float* b1 = (const float*)d_in[7];
  const float* W2 = (const float*)d_in[8];
  const float* b2 = (const float*)d_in[9];
  const float* P1 = (const float*)d_in[10];
  const float* pb1 = (const float*)d_in[11];
  const float* P2 = (const float*)d_in[12];
  const float* pb2 = (const float*)d_in[13];
  const float* U1 = (const float*)d_in[14];
  const float* ub1 = (const float*)d_in[15];
  const float* U2 = (const float*)d_in[16];
  const float* ub2 = (const float*)d_in[17];

  float* out_feat = (float*)d_out;
  float* out_pos = out_feat + (size_t)kNC * kH;

  size_t node_smem = (size_t)NODE_SMEM_FLOATS * sizeof(float);
  cudaFuncSetAttribute(msg_mma, cudaFuncAttributeMaxDynamicSharedMemorySize,
                       MSG_SMEM_BYTES);
  cudaFuncSetAttribute(node_kernel, cudaFuncAttributeMaxDynamicSharedMemorySize,
                       (int)node_smem);

  zero_kernel<<<(kNC * kH + 255) / 256, 256>>>();
  prep_kernel<<<(kNC + 255) / 256, 256>>>(positions, cni, mask);
  wfrag_kernel<<<9, 256>>>(W1, W2, P1);
  inv_kernel<<<(kNR + 255) / 256, 256>>>(positions, edge_index);
  msg_mma<<<kNR / TILE, TBM, MSG_SMEM_BYTES>>>(features, positions, edge_index,
                                               b1, b2, pb1, P2, pb2);
  node_kernel<<<(kNC + TILE - 1) / TILE, TB, node_smem>>>(
      features, degree, U1, ub1, U2, ub2, out_feat);
  pos_kernel<<<(kNC * kP + 255) / 256, 256>>>(positions, out_pos);
}

// round 8
// speedup vs baseline: 1.2821x; 1.2821x over previous
#include <cuda_runtime.h>
#include <math.h>

typedef unsigned long long ull;

namespace {
constexpr int kB = 2, kC = 20000, kH = 64, kM = 8, kE = 200000, kP = 3;
constexpr int kNR = kB * kE;      // 400000 message rows (3125 * 128 exactly)
constexpr int kNC = kB * kC;      // 40000 node rows
constexpr int kIn1 = 2 * kH + 4;  // 132
constexpr int TILE = 128;
constexpr int TBM = 256;          // msg block threads (8x4 reg tiles)
constexpr int TB = 512;           // node block threads

// msg_kernel shared layout (float offsets)
constexpr int OFF_W1 = 0;        // 132*64 = 8448
constexpr int OFF_W2 = 8448;     // 4096
constexpr int OFF_P1 = 12544;    // 4096
constexpr int OFF_P2 = 16640;    // 64
constexpr int OFF_B1 = 16704;    // 64
constexpr int OFF_B2 = 16768;    // 64
constexpr int OFF_PB1 = 16832;   // 64
constexpr int OFF_HM = 16896;    // 128*68 = 8704 (H, then reused as Msg)
constexpr int OFF_INV = 25600;   // 128*4
constexpr int OFF_REL = 26112;   // 128*3
constexpr int OFF_WT = 26496;    // 128
constexpr int OFF_DST = 26624;   // 128 (int)
constexpr int OFF_FS = 26752;    // 128 (int)
constexpr int OFF_FD = 26880;    // 128 (int)
constexpr int MSG_SMEM_FLOATS = 27008;  // 108,032 B -> 2 blocks/SM

// node_kernel shared layout
constexpr int NOFF_U1 = 0;       // 8192
constexpr int NOFF_U2 = 8192;    // 4096
constexpr int NOFF_UB1 = 12288;  // 64
constexpr int NOFF_UB2 = 12352;  // 64
constexpr int NOFF_HM = 12416;   // 8704
constexpr int NOFF_IDG = 21120;  // 128
constexpr int NODE_SMEM_FLOATS = 21248;  // 84,992 B -> 2 blocks/SM
}  // namespace

// Scratch (static device globals)
__device__ float g_agg[kNC * kH];
__device__ float g_posupd[kNC * kP];
__device__ float g_npos[kNC * kM * 3];
__device__ float g_np2[kNC * kM];
__device__ float g_cent[kNC * 3];
__device__ unsigned g_mbits[kC];

// ---- packed f32x2 helpers ----
__device__ __forceinline__ ull dup2(float v) {
  ull r;
  asm("mov.b64 %0, {%1, %1};" : "=l"(r) : "f"(v));
  return r;
}
__device__ __forceinline__ void ffma2(ull& d, ull a, ull b) {
  asm("fma.rn.f32x2 %0, %1, %2, %0;" : "+l"(d) : "l"(a), "l"(b));
}
__device__ __forceinline__ void fma2_scale_bias(ull& d, ull a, ull b) {
  asm("fma.rn.f32x2 %0, %0, %1, %2;" : "+l"(d) : "l"(a), "l"(b));
}
__device__ __forceinline__ float2 unpack2(ull v) {
  float2 f;
  asm("mov.b64 {%0, %1}, %2;" : "=f"(f.x), "=f"(f.y) : "l"(v));
  return f;
}
__device__ __forceinline__ void red_add_v4(float* p, float a, float b, float c,
                                           float d) {
  asm volatile("red.global.add.v4.f32 [%0], {%1, %2, %3, %4};" ::"l"(p), "f"(a),
               "f"(b), "f"(c), "f"(d)
               : "memory");
}

// silu via single-MUFU tanh.approx: silu(x) = 0.5x * (1 + tanh(x/2))
__device__ __forceinline__ float silu_f(float v) {
  float t;
  asm("tanh.approx.f32 %0, %1;" : "=f"(t) : "f"(0.5f * v));
  return 0.5f * v * (1.f + t);
}

// ---- 8-row x 4-col tile, 64 k-steps ----
__device__ __forceinline__ void gemm64_8(const float* const xp[8],
                                         const float* __restrict__ W, int cg,
                                         ull acc[8][2]) {
#pragma unroll
  for (int g = 0; g < 16; g++) {
    float4 xv[8];
#pragma unroll
    for (int r = 0; r < 8; r++) xv[r] = *(const float4*)(xp[r] + 4 * g);
#pragma unroll
    for (int kk = 0; kk < 4; kk++) {
      ulonglong2 w = *(const ulonglong2*)(W + (4 * g + kk) * 64 + cg * 4);
#pragma unroll
      for (int r = 0; r < 8; r++) {
        ull d = dup2(((const float*)&xv[r])[kk]);
        ffma2(acc[r][0], d, w.x);
        ffma2(acc[r][1], d, w.y);
      }
    }
  }
}

// 4-row version (node kernel)
__device__ __forceinline__ void gemm16(const float* __restrict__ x0,
                                       const float* __restrict__ x1,
                                       const float* __restrict__ x2,
                                       const float* __restrict__ x3,
                                       const float* __restrict__ W, int cg,
                                       ull acc[4][2]) {
#pragma unroll 2
  for (int g = 0; g < 16; g++) {
    float4 xv0 = *(const float4*)(x0 + 4 * g);
    float4 xv1 = *(const float4*)(x1 + 4 * g);
    float4 xv2 = *(const float4*)(x2 + 4 * g);
    float4 xv3 = *(const float4*)(x3 + 4 * g);
#pragma unroll
    for (int kk = 0; kk < 4; kk++) {
      ulonglong2 w = *(const ulonglong2*)(W + (4 * g + kk) * 64 + cg * 4);
      ull d0 = dup2(((const float*)&xv0)[kk]);
      ull d1 = dup2(((const float*)&xv1)[kk]);
      ull d2 = dup2(((const float*)&xv2)[kk]);
      ull d3 = dup2(((const float*)&xv3)[kk]);
      ffma2(acc[0][0], d0, w.x);
      ffma2(acc[0][1], d0, w.y);
      ffma2(acc[1][0], d1, w.x);
      ffma2(acc[1][1], d1, w.y);
      ffma2(acc[2][0], d2, w.x);
      ffma2(acc[2][1], d2, w.y);
      ffma2(acc[3][0], d3, w.x);
      ffma2(acc[3][1], d3, w.y);
    }
  }
}

__global__ void zero_kernel() {
  int i = blockIdx.x * blockDim.x + threadIdx.x;
  if (i < kNC * kH) g_agg[i] = 0.f;
  if (i < kNC * kP) g_posupd[i] = 0.f;
}

__global__ void prep_kernel(const float* __restrict__ positions,
                            const int* __restrict__ cni,
                            const float* __restrict__ mask) {
  int i = blockIdx.x * blockDim.x + threadIdx.x;
  if (i >= kNC) return;
  int b = i / kC, c = i - b * kC;
  float sx = 0.f, sy = 0.f, sz = 0.f, cnt = 0.f;
  unsigned bits = 0;
#pragma unroll
  for (int m = 0; m < kM; m++) {
    int idx = cni[c * kM + m];
    const float* p = positions + ((size_t)b * kC + idx) * kP;
    float x = p[0], y = p[1], z = p[2];
    g_npos[((size_t)i * kM + m) * 3 + 0] = x;
    g_npos[((size_t)i * kM + m) * 3 + 1] = y;
    g_npos[((size_t)i * kM + m) * 3 + 2] = z;
    g_np2[i * kM + m] = x * x + y * y + z * z;
    float mk = mask[c * kM + m];
    if (mk > 0.f) { bits |= (1u << m); sx += x; sy += y; sz += z; cnt += 1.f; }
  }
  float den = fmaxf(cnt, 1e-12f);
  g_cent[i * 3 + 0] = sx / den;
  g_cent[i * 3 + 1] = sy / den;
  g_cent[i * 3 + 2] = sz / den;
  if (b == 0) g_mbits[c] = bits;
}

__global__ void __launch_bounds__(TBM, 2) msg_kernel(
    const float* __restrict__ features, const float* __restrict__ positions,
    const int* __restrict__ ei,
    const float* __restrict__ W1, const float* __restrict__ b1,
    const float* __restrict__ W2, const float* __restrict__ b2,
    const float* __restrict__ P1, const float* __restrict__ pb1,
    const float* __restrict__ P2, const float* __restrict__ pb2) {
  extern __shared__ float sm[];
  float* sW1 = sm + OFF_W1;
  float* sW2 = sm + OFF_W2;
  float* sP1 = sm + OFF_P1;
  float* sP2 = sm + OFF_P2;
  float* sb1 = sm + OFF_B1;
  float* sb2 = sm + OFF_B2;
  float* spb1 = sm + OFF_PB1;
  float* sHM = sm + OFF_HM;    // [128][68] H, then Msg
  float* sInv = sm + OFF_INV;  // [128][4]
  float* sRel = sm + OFF_REL;
  float* sWt = sm + OFF_WT;
  int* sDst = (int*)(sm + OFF_DST);
  int* sFs = (int*)(sm + OFF_FS);
  int* sFd = (int*)(sm + OFF_FD);

  int tid = threadIdx.x;
  for (int i = tid; i < kIn1 * 64; i += TBM) sW1[i] = W1[i];
  for (int i = tid; i < 64 * 64; i += TBM) { sW2[i] = W2[i]; sP1[i] = P1[i]; }
  if (tid < 64) { sP2[tid] = P2[tid]; sb1[tid] = b1[tid]; sb2[tid] = b2[tid]; spb1[tid] = pb1[tid]; }
  float pb2v = pb2[0];

  // ---- gather (indices + rel) ----
  if (tid < TILE) {
    int gr = blockIdx.x * TILE + tid;
    int b = gr / kE, e = gr - b * kE;
    int src = ei[e], dst = ei[kE + e];
    int is = b * kC + src, id = b * kC + dst;
    sFs[tid] = is * kH;
    sFd[tid] = id * kH;
    sDst[tid] = id;
    const float* ps = positions + (size_t)is * kP;
    const float* pd = positions + (size_t)id * kP;
    sRel[tid * 3 + 0] = ps[0] - pd[0];
    sRel[tid * 3 + 1] = ps[1] - pd[1];
    sRel[tid * 3 + 2] = ps[2] - pd[2];
  }
  __syncthreads();

  // ---- fused invariants: 2 threads per row (MUFU work overlaps GEMM warps) ----
  {
    int row = tid >> 1, half = tid & 1;
    int is = sFs[row] >> 6;  // kH = 64
    int id = sDst[row];
    unsigned mx = g_mbits[is >= kC ? is - kC : is];
    unsigned my = g_mbits[id >= kC ? id - kC : id];
    float dp[24], dp2[8];
    {
      const float4* a = (const float4*)(g_npos + (size_t)id * 24);
#pragma unroll
      for (int q = 0; q < 6; q++) ((float4*)dp)[q] = a[q];
      const float4* d2 = (const float4*)(g_np2 + (size_t)id * 8);
      ((float4*)dp2)[0] = d2[0];
      ((float4*)dp2)[1] = d2[1];
    }
    float sp[12], sp2[4];
    {
      const float4* a = (const float4*)(g_npos + (size_t)is * 24 + half * 12);
#pragma unroll
      for (int q = 0; q < 3; q++) ((float4*)sp)[q] = a[q];
      ((float4*)sp2)[0] = *(const float4*)(g_np2 + (size_t)is * 8 + half * 4);
    }
    float colmin[8];
#pragma unroll
    for (int n = 0; n < 8; n++) colmin[n] = 3.4e38f;
    float pairwise = 0.f, hxy = 0.f;
    unsigned mxs = mx >> (half * 4);
#pragma unroll
    for (int m = 0; m < 4; m++) {
      if ((mxs >> m) & 1) {
        float rowmin = 3.4e38f;
        float ax = sp[m * 3], ay = sp[m * 3 + 1], az = sp[m * 3 + 2],
              a2 = sp2[m];
#pragma unroll
        for (int n = 0; n < 8; n++) {
          if ((my >> n) & 1) {
            float s = a2 + dp2[n] -
                      2.f * (ax * dp[n * 3] + ay * dp[n * 3 + 1] +
                             az * dp[n * 3 + 2]);
            float d = sqrtf(fmaxf(s, 0.f) + 1e-12f);
            pairwise += d;
            rowmin = fminf(rowmin, d);
            colmin[n] = fminf(colmin[n], d);
          }
        }
        hxy = fmaxf(hxy, rowmin);
      }
    }
    pairwise += __shfl_xor_sync(0xffffffffu, pairwise, 1);
    hxy = fmaxf(hxy, __shfl_xor_sync(0xffffffffu, hxy, 1));
#pragma unroll
    for (int n = 0; n < 8; n++)
      colmin[n] = fminf(colmin[n], __shfl_xor_sync(0xffffffffu, colmin[n], 1));
    if (half == 0) {
      float hyx = 0.f;
#pragma unroll
      for (int n = 0; n < 8; n++)
        if ((my >> n) & 1) hyx = fmaxf(hyx, colmin[n]);
      float haus = fmaxf(hxy, hyx);
      float c0 = g_cent[is * 3 + 0] - g_cent[id * 3 + 0];
      float c1 = g_cent[is * 3 + 1] - g_cent[id * 3 + 1];
      float c2 = g_cent[is * 3 + 2] - g_cent[id * 3 + 2];
      float centroid = sqrtf(c0 * c0 + c1 * c1 + c2 * c2);
      float r0 = sRel[row * 3 + 0], r1 = sRel[row * 3 + 1],
            r2 = sRel[row * 3 + 2];
      float dist = sqrtf(r0 * r0 + r1 * r1 + r2 * r2);
      ((float4*)sInv)[row] = make_float4(dist, pairwise, centroid, haus);
    }
  }
  __syncthreads();

  int rg = tid >> 4, cg = tid & 15;
  int row0 = rg * 8;
  ull acc[8][2];
#pragma unroll
  for (int i = 0; i < 8; i++) {
    acc[i][0] = *(const ull*)(sb1 + cg * 4 + 0);
    acc[i][1] = *(const ull*)(sb1 + cg * 4 + 2);
  }

  // ---- GEMM1: silu([h_src|h_dst|inv] @ W1 + b1) -> sHM ----
  {
    const float* xp[8];
#pragma unroll
    for (int r = 0; r < 8; r++) xp[r] = features + sFs[row0 + r];
    gemm64_8(xp, sW1, cg, acc);
#pragma unroll
    for (int r = 0; r < 8; r++) xp[r] = features + sFd[row0 + r];
    gemm64_8(xp, sW1 + 64 * 64, cg, acc);
    float4 iv[8];
#pragma unroll
    for (int r = 0; r < 8; r++) iv[r] = ((const float4*)sInv)[row0 + r];
#pragma unroll
    for (int kk = 0; kk < 4; kk++) {
      ulonglong2 w = *(const ulonglong2*)(sW1 + (128 + kk) * 64 + cg * 4);
#pragma unroll
      for (int r = 0; r < 8; r++) {
        ull d = dup2(((const float*)&iv[r])[kk]);
        ffma2(acc[r][0], d, w.x);
        ffma2(acc[r][1], d, w.y);
      }
    }
  }
#pragma unroll
  for (int i = 0; i < 8; i++)
#pragma unroll
    for (int p = 0; p < 2; p++) {
      float2 h = unpack2(acc[i][p]);
      h.x = silu_f(h.x);
      h.y = silu_f(h.y);
      *(float2*)(sHM + (row0 + i) * 68 + cg * 4 + 2 * p) = h;
    }
  __syncthreads();

  // ---- GEMM2: Msg = H @ W2 + b2 ----
#pragma unroll
  for (int i = 0; i < 8; i++) {
    acc[i][0] = *(const ull*)(sb2 + cg * 4 + 0);
    acc[i][1] = *(const ull*)(sb2 + cg * 4 + 2);
  }
  {
    const float* xp[8];
#pragma unroll
    for (int r = 0; r < 8; r++) xp[r] = sHM + (row0 + r) * 68;
    gemm64_8(xp, sW2, cg, acc);
  }
  __syncthreads();
#pragma unroll
  for (int i = 0; i < 8; i++)
#pragma unroll
    for (int p = 0; p < 2; p++) {
      float2 v = unpack2(acc[i][p]);
      *(float2*)(sHM + (row0 + i) * 68 + cg * 4 + 2 * p) = v;
    }
  __syncthreads();

  // ---- GEMM3: silu(Msg @ P1 + pb1) . P2, tanh -> wt ----
#pragma unroll
  for (int i = 0; i < 8; i++) {
    acc[i][0] = *(const ull*)(spb1 + cg * 4 + 0);
    acc[i][1] = *(const ull*)(spb1 + cg * 4 + 2);
  }
  {
    const float* xp[8];
#pragma unroll
    for (int r = 0; r < 8; r++) xp[r] = sHM + (row0 + r) * 68;
    gemm64_8(xp, sP1, cg, acc);
  }
  float part[8];
#pragma unroll
  for (int i = 0; i < 8; i++) {
    part[i] = 0.f;
#pragma unroll
    for (int p = 0; p < 2; p++) {
      float2 h = unpack2(acc[i][p]);
      part[i] = fmaf(silu_f(h.x), sP2[cg * 4 + 2 * p], part[i]);
      part[i] = fmaf(silu_f(h.y), sP2[cg * 4 + 2 * p + 1], part[i]);
    }
  }
#pragma unroll
  for (int i = 0; i < 8; i++) {
    float v = part[i];
    v += __shfl_xor_sync(0xffffffffu, v, 1);
    v += __shfl_xor_sync(0xffffffffu, v, 2);
    v += __shfl_xor_sync(0xffffffffu, v, 4);
    v += __shfl_xor_sync(0xffffffffu, v, 8);
    if (cg == 0) sWt[row0 + i] = tanhf(v + pb2v);
  }
  __syncthreads();

  // ---- scatter ----
  int lr = tid >> 1, ts = tid & 1;
  int ob = sDst[lr];
  float* ap = g_agg + (size_t)ob * kH + ts * 32;
  const float* mp = sHM + lr * 68 + ts * 32;
#pragma unroll
  for (int q = 0; q < 8; q++)
    red_add_v4(ap + q * 4, mp[q * 4 + 0], mp[q * 4 + 1], mp[q * 4 + 2],
               mp[q * 4 + 3]);
  if (ts == 0) {
    float w = sWt[lr];
    float* pp = g_posupd + (size_t)ob * kP;
    atomicAdd(pp + 0, w * sRel[lr * 3 + 0]);
    atomicAdd(pp + 1, w * sRel[lr * 3 + 1]);
    atomicAdd(pp + 2, w * sRel[lr * 3 + 2]);
  }
}

__global__ void __launch_bounds__(TB, 2) node_kernel(
    const float* __restrict__ features, const float* __restrict__ degree,
    const float* __restrict__ U1, const float* __restrict__ ub1,
    const float* __restrict__ U2, const float* __restrict__ ub2,
    float* __restrict__ out_feat) {
  extern __shared__ float smf[];
  float* sU1 = smf + NOFF_U1;
  float* sU2 = smf + NOFF_U2;
  float* sub1 = smf + NOFF_UB1;
  float* sub2 = smf + NOFF_UB2;
  float* sHM = smf + NOFF_HM;
  float* sInvD = smf + NOFF_IDG;

  int tid = threadIdx.x;
  for (int i = tid; i < 128 * 64; i += TB) sU1[i] = U1[i];
  for (int i = tid; i < 64 * 64; i += TB) sU2[i] = U2[i];
  if (tid < 64) { sub1[tid] = ub1[tid]; sub2[tid] = ub2[tid]; }

  if (tid < TILE) {
    int gr = blockIdx.x * TILE + tid;
    int grc = gr < kNC ? gr : kNC - 1;
    int c = grc % kC;
    sInvD[tid] = 1.f / fmaxf(degree[c], 1.f);
  }
  __syncthreads();

  int rg = tid >> 4, cg = tid & 15;
  int row0 = rg * 4;
  int gr0 = blockIdx.x * TILE + row0;
  int r0c = min(gr0 + 0, kNC - 1);
  int r1c = min(gr0 + 1, kNC - 1);
  int r2c = min(gr0 + 2, kNC - 1);
  int r3c = min(gr0 + 3, kNC - 1);

  ull acc[4][2];
#pragma unroll
  for (int i = 0; i < 4; i++) { acc[i][0] = 0ull; acc[i][1] = 0ull; }

  gemm16(g_agg + (size_t)r0c * kH, g_agg + (size_t)r1c * kH,
         g_agg + (size_t)r2c * kH, g_agg + (size_t)r3c * kH, sU1 + 64 * 64, cg,
         acc);
  {
    ull bias0 = *(const ull*)(sub1 + cg * 4 + 0);
    ull bias1 = *(const ull*)(sub1 + cg * 4 + 2);
#pragma unroll
    for (int i = 0; i < 4; i++) {
      ull dv = dup2(sInvD[row0 + i]);
      fma2_scale_bias(acc[i][0], dv, bias0);
      fma2_scale_bias(acc[i][1], dv, bias1);
    }
  }
  gemm16(features + (size_t)r0c * kH, features + (size_t)r1c * kH,
         features + (size_t)r2c * kH, features + (size_t)r3c * kH, sU1, cg,
         acc);
#pragma unroll
  for (int i = 0; i < 4; i++)
#pragma unroll
    for (int p = 0; p < 2; p++) {
      float2 h = unpack2(acc[i][p]);
      h.x = silu_f(h.x);
      h.y = silu_f(h.y);
      *(float2*)(sHM + (row0 + i) * 68 + cg * 4 + 2 * p) = h;
    }
  __syncthreads();

#pragma unroll
  for (int i = 0; i < 4; i++) {
    acc[i][0] = *(const ull*)(sub2 + cg * 4 + 0);
    acc[i][1] = *(const ull*)(sub2 + cg * 4 + 2);
  }
  gemm16(sHM + (row0 + 0) * 68, sHM + (row0 + 1) * 68, sHM + (row0 + 2) * 68,
         sHM + (row0 + 3) * 68, sU2, cg, acc);
#pragma unroll
  for (int i = 0; i < 4; i++) {
    int g2 = gr0 + i;
    if (g2 < kNC) {
      const float4 f = ((const float4*)(features + (size_t)g2 * kH))[cg];
      float2 v0 = unpack2(acc[i][0]);
      float2 v1 = unpack2(acc[i][1]);
      float4 o;
      o.x = f.x + v0.x;
      o.y = f.y + v0.y;
      o.z = f.z + v1.x;
      o.w = f.w + v1.y;
      ((float4*)(out_feat + (size_t)g2 * kH))[cg] = o;
    }
  }
}

__global__ void pos_kernel(const float* __restrict__ positions,
                           float* __restrict__ out_pos) {
  int i = blockIdx.x * blockDim.x + threadIdx.x;
  if (i < kNC * kP) out_pos[i] = positions[i] + g_posupd[i];
}

extern "C" void kernel_launch(void* const* d_in, const int* in_sizes, int n_in,
                              void* d_out, int out_size) {
  const float* features = (const float*)d_in[0];
  const float* positions = (const float*)d_in[1];
  const int* edge_index = (const int*)d_in[2];
  const float* degree = (const float*)d_in[3];
  const int* cni = (const int*)d_in[4];
  const float* mask = (const float*)d_in[5];
  const float* W1 = (const float*)d_in[6];
  const float* b1 = (const float*)d_in[7];
  const float* W2 = (const float*)d_in[8];
  const float* b2 = (const float*)d_in[9];
  const float* P1 = (const float*)d_in[10];
  const float* pb1 = (const float*)d_in[11];
  const float* P2 = (const float*)d_in[12];
  const float* pb2 = (const float*)d_in[13];
  const float* U1 = (const float*)d_in[14];
  const float* ub1 = (const float*)d_in[15];
  const float* U2 = (const float*)d_in[16];
  const float* ub2 = (const float*)d_in[17];

  float* out_feat = (float*)d_out;
  float* out_pos = out_feat + (size_t)kNC * kH;

  size_t msg_smem = (size_t)MSG_SMEM_FLOATS * sizeof(float);    // 108,032 B
  size_t node_smem = (size_t)NODE_SMEM_FLOATS * sizeof(float);  // 84,992 B
  cudaFuncSetAttribute(msg_kernel, cudaFuncAttributeMaxDynamicSharedMemorySize,
                       (int)msg_smem);
  cudaFuncSetAttribute(node_kernel, cudaFuncAttributeMaxDynamicSharedMemorySize,
                       (int)node_smem);

  zero_kernel<<<(kNC * kH + 255) / 256, 256>>>();
  prep_kernel<<<(kNC + 255) / 256, 256>>>(positions, cni, mask);
  msg_kernel<<<kNR / TILE, TBM, msg_smem>>>(features, positions, edge_index, W1,
                                            b1, W2, b2, P1, pb1, P2, pb2);
  node_kernel<<<(kNC + TILE - 1) / TILE, TB, node_smem>>>(
      features, degree, U1, ub1, U2, ub2, out_feat);
  pos_kernel<<<(kNC * kP + 255) / 256, 256>>>(positions, out_pos);
}

// round 9
// speedup vs baseline: 1.7465x; 1.3622x over previous
#include <cuda_runtime.h>
#include <math.h>

typedef unsigned long long ull;

namespace {
constexpr int kB = 2, kC = 20000, kH = 64, kM = 8, kE = 200000, kP = 3;
constexpr int kNR = kB * kE;  // 400000 = 3125 * 128
constexpr int kNC = kB * kC;  // 40000
constexpr int TILE = 128;
constexpr int TBM = 256;   // msg threads
constexpr int NTILE = 160; // node rows/block (250 blocks exact)
constexpr int TB = 512;    // node threads

// msg_kernel shared layout (float offsets)
constexpr int OFF_W1C = 0;      // 4*64 = 256
constexpr int OFF_W2 = 256;     // 4096
constexpr int OFF_P1 = 4352;    // 4096
constexpr int OFF_P2 = 8448;    // 64
constexpr int OFF_B1 = 8512;    // 64
constexpr int OFF_B2 = 8576;    // 64
constexpr int OFF_PB1 = 8640;   // 64
constexpr int OFF_HM = 8704;    // 128*68 = 8704 (H then Msg)
constexpr int OFF_INV = 17408;  // 128*4
constexpr int OFF_REL = 17920;  // 128*3 -> 384
constexpr int OFF_WT = 18304;   // 128
constexpr int OFF_DST = 18432;  // 128
constexpr int OFF_FS = 18560;   // 128
constexpr int OFF_FD = 18688;   // 128
constexpr int MSG_SMEM_FLOATS = 18816;  // 75,264 B -> 3 blocks/SM

// node_kernel shared layout
constexpr int NOFF_U1 = 0;       // 8192
constexpr int NOFF_U2 = 8192;    // 4096
constexpr int NOFF_UB1 = 12288;  // 64
constexpr int NOFF_UB2 = 12352;  // 64
constexpr int NOFF_HM = 12416;   // 160*68 = 10880
constexpr int NOFF_IDG = 23296;  // 160
constexpr int NODE_SMEM_FLOATS = 23456;  // 93,824 B -> 2 blocks/SM
}  // namespace

// Scratch (static device globals)
__device__ float g_agg[kNC * kH];
__device__ float g_posupd[kNC * kP];
__device__ float g_npos[kNC * kM * 3];
__device__ float g_np2[kNC * kM];
__device__ float g_cent[kNC * 3];
__device__ unsigned g_mbits[kC];
__device__ float g_fw[(size_t)kNC * 128];  // [node][0:64]=f@W1a, [64:128]=f@W1b

// ---- packed f32x2 helpers ----
__device__ __forceinline__ ull dup2(float v) {
  ull r;
  asm("mov.b64 %0, {%1, %1};" : "=l"(r) : "f"(v));
  return r;
}
__device__ __forceinline__ ull pack2f(float a, float b) {
  ull r;
  asm("mov.b64 %0, {%1, %2};" : "=l"(r) : "f"(a), "f"(b));
  return r;
}
__device__ __forceinline__ void ffma2(ull& d, ull a, ull b) {
  asm("fma.rn.f32x2 %0, %1, %2, %0;" : "+l"(d) : "l"(a), "l"(b));
}
__device__ __forceinline__ void fma2_scale_bias(ull& d, ull a, ull b) {
  asm("fma.rn.f32x2 %0, %0, %1, %2;" : "+l"(d) : "l"(a), "l"(b));
}
__device__ __forceinline__ float2 unpack2(ull v) {
  float2 f;
  asm("mov.b64 {%0, %1}, %2;" : "=f"(f.x), "=f"(f.y) : "l"(v));
  return f;
}
__device__ __forceinline__ void red_add_v4(float* p, float a, float b, float c,
                                           float d) {
  asm volatile("red.global.add.v4.f32 [%0], {%1, %2, %3, %4};" ::"l"(p), "f"(a),
               "f"(b), "f"(c), "f"(d)
               : "memory");
}
// silu via single-MUFU tanh.approx
__device__ __forceinline__ float silu_f(float v) {
  float t;
  asm("tanh.approx.f32 %0, %1;" : "=f"(t) : "f"(0.5f * v));
  return 0.5f * v * (1.f + t);
}

// R-row x 4-col tile, 64 k-steps, W row-major [64][64] in smem
template <int R>
__device__ __forceinline__ void gemm64r(const float* const xp[R],
                                        const float* __restrict__ W, int cg,
                                        ull (*acc)[2]) {
#pragma unroll
  for (int g = 0; g < 16; g++) {
    float4 xv[R];
#pragma unroll
    for (int r = 0; r < R; r++) xv[r] = *(const float4*)(xp[r] + 4 * g);
#pragma unroll
    for (int kk = 0; kk < 4; kk++) {
      ulonglong2 w = *(const ulonglong2*)(W + (4 * g + kk) * 64 + cg * 4);
#pragma unroll
      for (int r = 0; r < R; r++) {
        ull d = dup2(((const float*)&xv[r])[kk]);
        ffma2(acc[r][0], d, w.x);
        ffma2(acc[r][1], d, w.y);
      }
    }
  }
}

__global__ void zero_kernel() {
  int i = blockIdx.x * blockDim.x + threadIdx.x;
  if (i < kNC * kH) g_agg[i] = 0.f;
  if (i < kNC * kP) g_posupd[i] = 0.f;
}

__global__ void prep_kernel(const float* __restrict__ positions,
                            const int* __restrict__ cni,
                            const float* __restrict__ mask) {
  int i = blockIdx.x * blockDim.x + threadIdx.x;
  if (i >= kNC) return;
  int b = i / kC, c = i - b * kC;
  float sx = 0.f, sy = 0.f, sz = 0.f, cnt = 0.f;
  unsigned bits = 0;
#pragma unroll
  for (int m = 0; m < kM; m++) {
    int idx = cni[c * kM + m];
    const float* p = positions + ((size_t)b * kC + idx) * kP;
    float x = p[0], y = p[1], z = p[2];
    g_npos[((size_t)i * kM + m) * 3 + 0] = x;
    g_npos[((size_t)i * kM + m) * 3 + 1] = y;
    g_npos[((size_t)i * kM + m) * 3 + 2] = z;
    g_np2[i * kM + m] = x * x + y * y + z * z;
    float mk = mask[c * kM + m];
    if (mk > 0.f) { bits |= (1u << m); sx += x; sy += y; sz += z; cnt += 1.f; }
  }
  float den = fmaxf(cnt, 1e-12f);
  g_cent[i * 3 + 0] = sx / den;
  g_cent[i * 3 + 1] = sy / den;
  g_cent[i * 3 + 2] = sz / den;
  if (b == 0) g_mbits[c] = bits;
}

// F[node] = [features@W1a | features@W1b]  (hoisted GEMM1 node terms)
__global__ void __launch_bounds__(512) featw_kernel(
    const float* __restrict__ features, const float* __restrict__ W1) {
  __shared__ float sW[64 * 128];
  int tid = threadIdx.x;
  for (int i = tid; i < 64 * 128; i += 512) {
    int k = i >> 7, n = i & 127;
    sW[i] = (n < 64) ? W1[k * 64 + n] : W1[(64 + k) * 64 + (n - 64)];
  }
  __syncthreads();
  int rg = tid >> 5, cg = tid & 31;
  int row0 = blockIdx.x * 80 + rg * 5;
  ull acc[5][2];
#pragma unroll
  for (int r = 0; r < 5; r++) { acc[r][0] = 0ull; acc[r][1] = 0ull; }
  const float* xp[5];
#pragma unroll
  for (int r = 0; r < 5; r++) xp[r] = features + (size_t)(row0 + r) * kH;
#pragma unroll
  for (int g = 0; g < 16; g++) {
    float4 xv[5];
#pragma unroll
    for (int r = 0; r < 5; r++) xv[r] = *(const float4*)(xp[r] + 4 * g);
#pragma unroll
    for (int kk = 0; kk < 4; kk++) {
      ulonglong2 w = *(const ulonglong2*)(sW + (4 * g + kk) * 128 + cg * 4);
#pragma unroll
      for (int r = 0; r < 5; r++) {
        ull d = dup2(((const float*)&xv[r])[kk]);
        ffma2(acc[r][0], d, w.x);
        ffma2(acc[r][1], d, w.y);
      }
    }
  }
#pragma unroll
  for (int r = 0; r < 5; r++) {
    float2 v0 = unpack2(acc[r][0]);
    float2 v1 = unpack2(acc[r][1]);
    *(float4*)(g_fw + (size_t)(row0 + r) * 128 + cg * 4) =
        make_float4(v0.x, v0.y, v1.x, v1.y);
  }
}

__global__ void __launch_bounds__(TBM, 3) msg_kernel(
    const float* __restrict__ features, const float* __restrict__ positions,
    const int* __restrict__ ei,
    const float* __restrict__ W1, const float* __restrict__ b1,
    const float* __restrict__ W2, const float* __restrict__ b2,
    const float* __restrict__ P1, const float* __restrict__ pb1,
    const float* __restrict__ P2, const float* __restrict__ pb2) {
  extern __shared__ float sm[];
  float* sW1c = sm + OFF_W1C;
  float* sW2 = sm + OFF_W2;
  float* sP1 = sm + OFF_P1;
  float* sP2 = sm + OFF_P2;
  float* sb1 = sm + OFF_B1;
  float* sb2 = sm + OFF_B2;
  float* spb1 = sm + OFF_PB1;
  float* sHM = sm + OFF_HM;    // [128][68] H, then Msg
  float* sInv = sm + OFF_INV;  // [128][4]
  float* sRel = sm + OFF_REL;
  float* sWt = sm + OFF_WT;
  int* sDst = (int*)(sm + OFF_DST);
  int* sFs = (int*)(sm + OFF_FS);
  int* sFd = (int*)(sm + OFF_FD);

  int tid = threadIdx.x;
  for (int i = tid; i < 256; i += TBM) sW1c[i] = W1[128 * 64 + i];
  for (int i = tid; i < 64 * 64; i += TBM) { sW2[i] = W2[i]; sP1[i] = P1[i]; }
  if (tid < 64) { sP2[tid] = P2[tid]; sb1[tid] = b1[tid]; sb2[tid] = b2[tid]; spb1[tid] = pb1[tid]; }
  float pb2v = pb2[0];

  // ---- gather (node indices + rel) ----
  if (tid < TILE) {
    int gr = blockIdx.x * TILE + tid;
    int b = gr / kE, e = gr - b * kE;
    int src = ei[e], dst = ei[kE + e];
    int is = b * kC + src, id = b * kC + dst;
    sFs[tid] = is;
    sFd[tid] = id;
    sDst[tid] = id;
    const float* ps = positions + (size_t)is * kP;
    const float* pd = positions + (size_t)id * kP;
    sRel[tid * 3 + 0] = ps[0] - pd[0];
    sRel[tid * 3 + 1] = ps[1] - pd[1];
    sRel[tid * 3 + 2] = ps[2] - pd[2];
  }
  __syncthreads();

  // ---- fused invariants: 2 threads per row ----
  {
    int row = tid >> 1, half = tid & 1;
    int is = sFs[row], id = sFd[row];
    unsigned mx = g_mbits[is >= kC ? is - kC : is];
    unsigned my = g_mbits[id >= kC ? id - kC : id];
    float dp[24], dp2[8];
    {
      const float4* a = (const float4*)(g_npos + (size_t)id * 24);
#pragma unroll
      for (int q = 0; q < 6; q++) ((float4*)dp)[q] = a[q];
      const float4* d2 = (const float4*)(g_np2 + (size_t)id * 8);
      ((float4*)dp2)[0] = d2[0];
      ((float4*)dp2)[1] = d2[1];
    }
    float sp[12], sp2[4];
    {
      const float4* a = (const float4*)(g_npos + (size_t)is * 24 + half * 12);
#pragma unroll
      for (int q = 0; q < 3; q++) ((float4*)sp)[q] = a[q];
      ((float4*)sp2)[0] = *(const float4*)(g_np2 + (size_t)is * 8 + half * 4);
    }
    float colmin[8];
#pragma unroll
    for (int n = 0; n < 8; n++) colmin[n] = 3.4e38f;
    float pairwise = 0.f, hxy = 0.f;
    unsigned mxs = mx >> (half * 4);
#pragma unroll
    for (int m = 0; m < 4; m++) {
      if ((mxs >> m) & 1) {
        float rowmin = 3.4e38f;
        float ax = sp[m * 3], ay = sp[m * 3 + 1], az = sp[m * 3 + 2],
              a2 = sp2[m];
#pragma unroll
        for (int n = 0; n < 8; n++) {
          if ((my >> n) & 1) {
            float s = a2 + dp2[n] -
                      2.f * (ax * dp[n * 3] + ay * dp[n * 3 + 1] +
                             az * dp[n * 3 + 2]);
            float d = sqrtf(fmaxf(s, 0.f) + 1e-12f);
            pairwise += d;
            rowmin = fminf(rowmin, d);
            colmin[n] = fminf(colmin[n], d);
          }
        }
        hxy = fmaxf(hxy, rowmin);
      }
    }
    pairwise += __shfl_xor_sync(0xffffffffu, pairwise, 1);
    hxy = fmaxf(hxy, __shfl_xor_sync(0xffffffffu, hxy, 1));
#pragma unroll
    for (int n = 0; n < 8; n++)
      colmin[n] = fminf(colmin[n], __shfl_xor_sync(0xffffffffu, colmin[n], 1));
    if (half == 0) {
      float hyx = 0.f;
#pragma unroll
      for (int n = 0; n < 8; n++)
        if ((my >> n) & 1) hyx = fmaxf(hyx, colmin[n]);
      float haus = fmaxf(hxy, hyx);
      float c0 = g_cent[is * 3 + 0] - g_cent[id * 3 + 0];
      float c1 = g_cent[is * 3 + 1] - g_cent[id * 3 + 1];
      float c2 = g_cent[is * 3 + 2] - g_cent[id * 3 + 2];
      float centroid = sqrtf(c0 * c0 + c1 * c1 + c2 * c2);
      float r0 = sRel[row * 3 + 0], r1 = sRel[row * 3 + 1],
            r2 = sRel[row * 3 + 2];
      float dist = sqrtf(r0 * r0 + r1 * r1 + r2 * r2);
      ((float4*)sInv)[row] = make_float4(dist, pairwise, centroid, haus);
    }
  }
  __syncthreads();

  int rg = tid >> 4, cg = tid & 15;
  int row0 = rg * 8;
  ull acc[8][2];

  // ---- GEMM1 (hoisted): acc = b1 + F[src] + F[dst] + inv@W1c ----
  {
    float bb0 = sb1[cg * 4 + 0], bb1 = sb1[cg * 4 + 1];
    float bb2 = sb1[cg * 4 + 2], bb3 = sb1[cg * 4 + 3];
#pragma unroll
    for (int r = 0; r < 8; r++) {
      int is = sFs[row0 + r], id = sFd[row0 + r];
      float4 fs = *(const float4*)(g_fw + (size_t)is * 128 + cg * 4);
      float4 fd = *(const float4*)(g_fw + (size_t)id * 128 + 64 + cg * 4);
      acc[r][0] = pack2f(bb0 + fs.x + fd.x, bb1 + fs.y + fd.y);
      acc[r][1] = pack2f(bb2 + fs.z + fd.z, bb3 + fs.w + fd.w);
    }
    float4 iv[8];
#pragma unroll
    for (int r = 0; r < 8; r++) iv[r] = ((const float4*)sInv)[row0 + r];
#pragma unroll
    for (int kk = 0; kk < 4; kk++) {
      ulonglong2 w = *(const ulonglong2*)(sW1c + kk * 64 + cg * 4);
#pragma unroll
      for (int r = 0; r < 8; r++) {
        ull d = dup2(((const float*)&iv[r])[kk]);
        ffma2(acc[r][0], d, w.x);
        ffma2(acc[r][1], d, w.y);
      }
    }
  }
#pragma unroll
  for (int i = 0; i < 8; i++)
#pragma unroll
    for (int p = 0; p < 2; p++) {
      float2 h = unpack2(acc[i][p]);
      h.x = silu_f(h.x);
      h.y = silu_f(h.y);
      *(float2*)(sHM + (row0 + i) * 68 + cg * 4 + 2 * p) = h;
    }
  __syncthreads();

  // ---- GEMM2: Msg = H @ W2 + b2 ----
#pragma unroll
  for (int i = 0; i < 8; i++) {
    acc[i][0] = *(const ull*)(sb2 + cg * 4 + 0);
    acc[i][1] = *(const ull*)(sb2 + cg * 4 + 2);
  }
  {
    const float* xp[8];
#pragma unroll
    for (int r = 0; r < 8; r++) xp[r] = sHM + (row0 + r) * 68;
    gemm64r<8>(xp, sW2, cg, acc);
  }
  __syncthreads();
#pragma unroll
  for (int i = 0; i < 8; i++)
#pragma unroll
    for (int p = 0; p < 2; p++) {
      float2 v = unpack2(acc[i][p]);
      *(float2*)(sHM + (row0 + i) * 68 + cg * 4 + 2 * p) = v;
    }
  __syncthreads();

  // ---- GEMM3: silu(Msg @ P1 + pb1) . P2, tanh -> wt ----
#pragma unroll
  for (int i = 0; i < 8; i++) {
    acc[i][0] = *(const ull*)(spb1 + cg * 4 + 0);
    acc[i][1] = *(const ull*)(spb1 + cg * 4 + 2);
  }
  {
    const float* xp[8];
#pragma unroll
    for (int r = 0; r < 8; r++) xp[r] = sHM + (row0 + r) * 68;
    gemm64r<8>(xp, sP1, cg, acc);
  }
  float part[8];
#pragma unroll
  for (int i = 0; i < 8; i++) {
    part[i] = 0.f;
#pragma unroll
    for (int p = 0; p < 2; p++) {
      float2 h = unpack2(acc[i][p]);
      part[i] = fmaf(silu_f(h.x), sP2[cg * 4 + 2 * p], part[i]);
      part[i] = fmaf(silu_f(h.y), sP2[cg * 4 + 2 * p + 1], part[i]);
    }
  }
#pragma unroll
  for (int i = 0; i < 8; i++) {
    float v = part[i];
    v += __shfl_xor_sync(0xffffffffu, v, 1);
    v += __shfl_xor_sync(0xffffffffu, v, 2);
    v += __shfl_xor_sync(0xffffffffu, v, 4);
    v += __shfl_xor_sync(0xffffffffu, v, 8);
    if (cg == 0) sWt[row0 + i] = tanhf(v + pb2v);
  }
  __syncthreads();

  // ---- scatter ----
  int lr = tid >> 1, ts = tid & 1;
  int ob = sDst[lr];
  float* ap = g_agg + (size_t)ob * kH + ts * 32;
  const float* mp = sHM + lr * 68 + ts * 32;
#pragma unroll
  for (int q = 0; q < 8; q++)
    red_add_v4(ap + q * 4, mp[q * 4 + 0], mp[q * 4 + 1], mp[q * 4 + 2],
               mp[q * 4 + 3]);
  if (ts == 0) {
    float w = sWt[lr];
    float* pp = g_posupd + (size_t)ob * kP;
    atomicAdd(pp + 0, w * sRel[lr * 3 + 0]);
    atomicAdd(pp + 1, w * sRel[lr * 3 + 1]);
    atomicAdd(pp + 2, w * sRel[lr * 3 + 2]);
  }
}

__global__ void __launch_bounds__(TB, 2) node_kernel(
    const float* __restrict__ features, const float* __restrict__ degree,
    const float* __restrict__ U1, const float* __restrict__ ub1,
    const float* __restrict__ U2, const float* __restrict__ ub2,
    float* __restrict__ out_feat) {
  extern __shared__ float smf[];
  float* sU1 = smf + NOFF_U1;
  float* sU2 = smf + NOFF_U2;
  float* sub1 = smf + NOFF_UB1;
  float* sub2 = smf + NOFF_UB2;
  float* sHM = smf + NOFF_HM;  // [160][68]
  float* sInvD = smf + NOFF_IDG;

  int tid = threadIdx.x;
  for (int i = tid; i < 128 * 64; i += TB) sU1[i] = U1[i];
  for (int i = tid; i < 64 * 64; i += TB) sU2[i] = U2[i];
  if (tid < 64) { sub1[tid] = ub1[tid]; sub2[tid] = ub2[tid]; }

  if (tid < NTILE) {
    int gr = blockIdx.x * NTILE + tid;
    int c = gr % kC;
    sInvD[tid] = 1.f / fmaxf(degree[c], 1.f);
  }
  __syncthreads();

  int rg = tid >> 4, cg = tid & 15;
  int row0 = rg * 5;
  int gr0 = blockIdx.x * NTILE + row0;

  ull acc[5][2];
#pragma unroll
  for (int i = 0; i < 5; i++) { acc[i][0] = 0ull; acc[i][1] = 0ull; }

  // agg part first (unscaled), then acc = acc*invd + bias, then features part
  {
    const float* xp[5];
#pragma unroll
    for (int r = 0; r < 5; r++) xp[r] = g_agg + (size_t)(gr0 + r) * kH;
    gemm64r<5>(xp, sU1 + 64 * 64, cg, acc);
  }
  {
    ull bias0 = *(const ull*)(sub1 + cg * 4 + 0);
    ull bias1 = *(const ull*)(sub1 + cg * 4 + 2);
#pragma unroll
    for (int i = 0; i < 5; i++) {
      ull dv = dup2(sInvD[row0 + i]);
      fma2_scale_bias(acc[i][0], dv, bias0);
      fma2_scale_bias(acc[i][1], dv, bias1);
    }
  }
  {
    const float* xp[5];
#pragma unroll
    for (int r = 0; r < 5; r++) xp[r] = features + (size_t)(gr0 + r) * kH;
    gemm64r<5>(xp, sU1, cg, acc);
  }
#pragma unroll
  for (int i = 0; i < 5; i++)
#pragma unroll
    for (int p = 0; p < 2; p++) {
      float2 h = unpack2(acc[i][p]);
      h.x = silu_f(h.x);
      h.y = silu_f(h.y);
      *(float2*)(sHM + (row0 + i) * 68 + cg * 4 + 2 * p) = h;
    }
  __syncthreads();

#pragma unroll
  for (int i = 0; i < 5; i++) {
    acc[i][0] = *(const ull*)(sub2 + cg * 4 + 0);
    acc[i][1] = *(const ull*)(sub2 + cg * 4 + 2);
  }
  {
    const float* xp[5];
#pragma unroll
    for (int r = 0; r < 5; r++) xp[r] = sHM + (row0 + r) * 68;
    gemm64r<5>(xp, sU2, cg, acc);
  }
#pragma unroll
  for (int i = 0; i < 5; i++) {
    int g2 = gr0 + i;
    const float4 f = ((const float4*)(features + (size_t)g2 * kH))[cg];
    float2 v0 = unpack2(acc[i][0]);
    float2 v1 = unpack2(acc[i][1]);
    float4 o;
    o.x = f.x + v0.x;
    o.y = f.y + v0.y;
    o.z = f.z + v1.x;
    o.w = f.w + v1.y;
    ((float4*)(out_feat + (size_t)g2 * kH))[cg] = o;
  }
}

__global__ void pos_kernel(const float* __restrict__ positions,
                           float* __restrict__ out_pos) {
  int i = blockIdx.x * blockDim.x + threadIdx.x;
  if (i < kNC * kP) out_pos[i] = positions[i] + g_posupd[i];
}

extern "C" void kernel_launch(void* const* d_in, const int* in_sizes, int n_in,
                              void* d_out, int out_size) {
  const float* features = (const float*)d_in[0];
  const float* positions = (const float*)d_in[1];
  const int* edge_index = (const int*)d_in[2];
  const float* degree = (const float*)d_in[3];
  const int* cni = (const int*)d_in[4];
  const float* mask = (const float*)d_in[5];
  const float* W1 = (const float*)d_in[6];
  const float* b1 = (const float*)d_in[7];
  const float* W2 = (const float*)d_in[8];
  const float* b2 = (const float*)d_in[9];
  const float* P1 = (const float*)d_in[10];
  const float* pb1 = (const float*)d_in[11];
  const float* P2 = (const float*)d_in[12];
  const float* pb2 = (const float*)d_in[13];
  const float* U1 = (const float*)d_in[14];
  const float* ub1 = (const float*)d_in[15];
  const float* U2 = (const float*)d_in[16];
  const float* ub2 = (const float*)d_in[17];

  float* out_feat = (float*)d_out;
  float* out_pos = out_feat + (size_t)kNC * kH;

  size_t msg_smem = (size_t)MSG_SMEM_FLOATS * sizeof(float);    // 75,264 B
  size_t node_smem = (size_t)NODE_SMEM_FLOATS * sizeof(float);  // 93,824 B
  cudaFuncSetAttribute(msg_kernel, cudaFuncAttributeMaxDynamicSharedMemorySize,
                       (int)msg_smem);
  cudaFuncSetAttribute(node_kernel, cudaFuncAttributeMaxDynamicSharedMemorySize,
                       (int)node_smem);

  zero_kernel<<<(kNC * kH + 255) / 256, 256>>>();
  prep_kernel<<<(kNC + 255) / 256, 256>>>(positions, cni, mask);
  featw_kernel<<<kNC / 80, 512>>>(features, W1);
  msg_kernel<<<kNR / TILE, TBM, msg_smem>>>(features, positions, edge_index, W1,
                                            b1, W2, b2, P1, pb1, P2, pb2);
  node_kernel<<<kNC / NTILE, TB, node_smem>>>(features, degree, U1, ub1, U2,
                                              ub2, out_feat);
  pos_kernel<<<(kNC * kP + 255) / 256, 256>>>(positions, out_pos);
}